// round 2
// baseline (speedup 1.0000x reference)
#include <cuda_runtime.h>
#include <cuda_bf16.h>
#include <cstdint>

// Problem dims
#define BB   2048
#define TT   128
#define FF   64
#define HH   512
#define G4   2048   // 4*H

// GEMM tile config
#define BM   128
#define BN   128    // = 4 gates x 32 h-cols
#define BK   16
#define NTHREADS 256
#define GSTRIDE 132  // gate staging stride

// Persistent state
__device__ float g_h1[2][BB * HH];
__device__ float g_c1[BB * HH];
__device__ float g_h2[2][BB * HH];
__device__ float g_c2[BB * HH];

// Fragment-major shared tiles: A = 512 float4 (8KB), B = 512 float4 (8KB), double buffered.
struct SMemMM {
    float A[2][2048];
    float B[2][2048];
};
union SMemU {
    SMemMM mm;
    float gs[64 * GSTRIDE];
};

__device__ __forceinline__ float to_tf32(float x) {
    uint32_t u;
    asm("cvt.rna.tf32.f32 %0, %1;" : "=r"(u) : "f"(x));
    return __uint_as_float(u);
}

__device__ __forceinline__ void mma8(float* d, const uint32_t* a, const uint32_t* b) {
    asm volatile(
        "mma.sync.aligned.m16n8k8.row.col.f32.tf32.tf32.f32 "
        "{%0,%1,%2,%3}, {%4,%5,%6,%7}, {%8,%9}, {%0,%1,%2,%3};\n"
        : "+f"(d[0]), "+f"(d[1]), "+f"(d[2]), "+f"(d[3])
        : "r"(a[0]), "r"(a[1]), "r"(a[2]), "r"(a[3]),
          "r"(b[0]), "r"(b[1]));
}

// A fragment float4 slot index (in float4 units):
//   ((warp_m*2 + kk)*4 + mm)*32 + (tig*8 + gid)
// element within float4: chalf*2 + rhalf
// holds {A[r][c], A[r+8][c], A[r][c+4], A[r+8][c+4]} for r = warp_m*64+mm*16+gid, c = kk*8+tig
//
// B fragment float4 slot index:
//   ((warp_n*4 + nn)*32 + blane), blane = (gid&3)*8 + tig*2 + (gid>>2)
// element = kh, holds B[kh*4 + tig][col] for col = warp_n*32 + nn*8 + gid, kh = 0..3

__global__ __launch_bounds__(NTHREADS, 2) void lstm_step_kernel(
    const float* __restrict__ Ax, int sAx, int KxT,
    const float* __restrict__ Ah, int KhT,
    const float* __restrict__ Wx, const float* __restrict__ Wu,
    const float* __restrict__ bias,
    float* __restrict__ cbuf, int zero_c,
    float* __restrict__ hout)
{
    __shared__ __align__(16) SMemU sm;

    const int tid    = threadIdx.x;
    const int lane   = tid & 31;
    const int warp   = tid >> 5;
    const int warp_m = warp >> 2;   // 0..1
    const int warp_n = warp & 3;    // 0..3
    const int gid    = lane >> 2;   // 0..7
    const int tig    = lane & 3;    // 0..3
    const int bm     = blockIdx.x * BM;
    const int h0     = blockIdx.y * 32;
    const int KT     = KxT + KhT;

    float acc[4][4][4] = {};

    // ---- A loader mapping ----
    const int a_row = tid >> 2;          // 0..63 (and +64)
    const int a_c4  = (tid & 3) * 4;
    const int a_mm  = (a_row >> 4) & 3;
    const int a_gid = a_row & 7;
    const int a_rh  = (a_row >> 3) & 1;

    // ---- B loader mapping: q = tid + it*256 -> (m, kl, gate, kh) ----
    int b_m[2], b_kl[2], b_gate[2], b_kh[2];
#pragma unroll
    for (int it = 0; it < 2; it++) {
        int q = tid + it * 256;
        b_m[it]    = q & 7;
        b_kl[it]   = (q >> 3) & 3;
        b_gate[it] = (q >> 5) & 3;
        b_kh[it]   = q >> 7;
    }

    // compute-side fragment lanes
    const int alane = tig * 8 + gid;
    const int blane = (gid & 3) * 8 + tig * 2 + (gid >> 2);

    float4 pa0, pa1, pb[2];

    auto load_tiles = [&](int kt) {
        const float* asrc; int astr; int krow;
        const float* wsrc;
        if (kt < KxT) { asrc = Ax; astr = sAx; krow = kt * BK; wsrc = Wx; }
        else          { asrc = Ah; astr = HH;  krow = (kt - KxT) * BK; wsrc = Wu; }
        pa0 = *(const float4*)(asrc + (size_t)(bm + a_row)      * astr + krow + a_c4);
        pa1 = *(const float4*)(asrc + (size_t)(bm + a_row + 64) * astr + krow + a_c4);
#pragma unroll
        for (int it = 0; it < 2; it++) {
            int k = b_kh[it] * 4 + b_kl[it];
            pb[it] = *(const float4*)(wsrc + (size_t)(krow + k) * G4
                                      + b_gate[it] * 512 + h0 + b_m[it] * 4);
        }
    };

    auto store_tiles = [&](int buf) {
        float* As = sm.mm.A[buf];
        float* Bs = sm.mm.B[buf];
        // A: scatter 4 scalars per row-half
        float av0[4] = { pa0.x, pa0.y, pa0.z, pa0.w };
        float av1[4] = { pa1.x, pa1.y, pa1.z, pa1.w };
#pragma unroll
        for (int j = 0; j < 4; j++) {
            int c  = a_c4 + j;
            int kk = c >> 3;
            int el = ((c >> 2) & 1) * 2 + a_rh;
            int lj = j * 8 + a_gid;
            As[(((0 * 2 + kk) * 4 + a_mm) * 32 + lj) * 4 + el] = to_tf32(av0[j]);
            As[(((1 * 2 + kk) * 4 + a_mm) * 32 + lj) * 4 + el] = to_tf32(av1[j]);
        }
        // B: scatter 4 scalars per loaded float4
#pragma unroll
        for (int it = 0; it < 2; it++) {
            float bv[4] = { pb[it].x, pb[it].y, pb[it].z, pb[it].w };
#pragma unroll
            for (int j = 0; j < 4; j++) {
                int cl = b_m[it] * 4 + j;
                int nn = cl >> 3;
                int gd = cl & 7;
                int bl = (gd & 3) * 8 + b_kl[it] * 2 + (gd >> 2);
                Bs[((b_gate[it] * 4 + nn) * 32 + bl) * 4 + b_kh[it]] = to_tf32(bv[j]);
            }
        }
    };

    auto compute = [&](int buf) {
        const float* As = sm.mm.A[buf];
        const float* Bs = sm.mm.B[buf];
        // B fragments: one float4 per nn covers both kk halves
        float4 bf[4];
#pragma unroll
        for (int nn = 0; nn < 4; nn++)
            bf[nn] = *(const float4*)(Bs + ((warp_n * 4 + nn) * 32 + blane) * 4);
#pragma unroll
        for (int kk = 0; kk < 2; kk++) {
            uint32_t afr[4][4];
#pragma unroll
            for (int mm = 0; mm < 4; mm++) {
                float4 av = *(const float4*)(As + (((warp_m * 2 + kk) * 4 + mm) * 32 + alane) * 4);
                afr[mm][0] = __float_as_uint(av.x);
                afr[mm][1] = __float_as_uint(av.y);
                afr[mm][2] = __float_as_uint(av.z);
                afr[mm][3] = __float_as_uint(av.w);
            }
#pragma unroll
            for (int mm = 0; mm < 4; mm++)
#pragma unroll
                for (int nn = 0; nn < 4; nn++) {
                    uint32_t bfr[2];
                    if (kk == 0) {
                        bfr[0] = __float_as_uint(bf[nn].x);
                        bfr[1] = __float_as_uint(bf[nn].y);
                    } else {
                        bfr[0] = __float_as_uint(bf[nn].z);
                        bfr[1] = __float_as_uint(bf[nn].w);
                    }
                    mma8(acc[mm][nn], afr[mm], bfr);
                }
        }
    };

    // ---- main loop: double-buffered ----
    load_tiles(0);
    store_tiles(0);
    __syncthreads();
#pragma unroll 1
    for (int kt = 0; kt < KT; kt++) {
        const int buf = kt & 1;
        const bool more = (kt + 1 < KT);
        if (more) load_tiles(kt + 1);
        compute(buf);
        if (more) store_tiles(buf ^ 1);
        __syncthreads();
    }

    // ---- epilogue: stage gates via smem, fused cell update ----
#pragma unroll 1
    for (int chunk = 0; chunk < 2; chunk++) {
        if (warp_m == chunk) {
#pragma unroll
            for (int mm = 0; mm < 4; mm++) {
#pragma unroll
                for (int nn = 0; nn < 4; nn++) {
                    int r  = mm * 16 + gid;
                    int cb = warp_n * 32 + nn * 8 + 2 * tig;
                    sm.gs[r * GSTRIDE + cb]           = acc[mm][nn][0];
                    sm.gs[r * GSTRIDE + cb + 1]       = acc[mm][nn][1];
                    sm.gs[(r + 8) * GSTRIDE + cb]     = acc[mm][nn][2];
                    sm.gs[(r + 8) * GSTRIDE + cb + 1] = acc[mm][nn][3];
                }
            }
        }
        __syncthreads();
#pragma unroll
        for (int i = 0; i < 8; i++) {
            int q = tid + i * 256;
            int r = q >> 5;
            int h = q & 31;
            int gh = h0 + h;
            float gi = sm.gs[r * GSTRIDE + h]      + bias[gh];
            float gf = sm.gs[r * GSTRIDE + 32 + h] + bias[512 + gh];
            float gc = sm.gs[r * GSTRIDE + 64 + h] + bias[1024 + gh];
            float go = sm.gs[r * GSTRIDE + 96 + h] + bias[1536 + gh];
            gi = 1.f / (1.f + __expf(-gi));
            gf = 1.f / (1.f + __expf(-gf));
            go = 1.f / (1.f + __expf(-go));
            gc = fmaxf(gc, 0.f);
            size_t ci = (size_t)(bm + chunk * 64 + r) * HH + gh;
            float cold = zero_c ? 0.f : cbuf[ci];
            float cn = gf * cold + gi * gc;
            cbuf[ci] = cn;
            hout[ci] = go * fmaxf(cn, 0.f);
        }
        __syncthreads();
    }
}

// Final dense head
__global__ __launch_bounds__(256) void dense_kernel(
    const float* __restrict__ h2, const float* __restrict__ Wd,
    const float* __restrict__ bd, float* __restrict__ out)
{
    int row  = blockIdx.x * 8 + (threadIdx.x >> 5);
    int lane = threadIdx.x & 31;
    const float* hr = h2 + (size_t)row * HH;
    float s = 0.f;
#pragma unroll
    for (int k = lane; k < HH; k += 32) s += hr[k] * Wd[k];
#pragma unroll
    for (int o = 16; o; o >>= 1) s += __shfl_xor_sync(0xffffffffu, s, o);
    if (lane == 0) out[row] = s + bd[0];
}

extern "C" void kernel_launch(void* const* d_in, const int* in_sizes, int n_in,
                              void* d_out, int out_size)
{
    (void)in_sizes; (void)n_in; (void)out_size;
    const float* x  = (const float*)d_in[0];
    const float* W1 = (const float*)d_in[1];
    const float* U1 = (const float*)d_in[2];
    const float* b1 = (const float*)d_in[3];
    const float* W2 = (const float*)d_in[4];
    const float* U2 = (const float*)d_in[5];
    const float* b2 = (const float*)d_in[6];
    const float* Wd = (const float*)d_in[7];
    const float* bd = (const float*)d_in[8];

    float *ph1, *pc1, *ph2, *pc2;
    cudaGetSymbolAddress((void**)&ph1, g_h1);
    cudaGetSymbolAddress((void**)&pc1, g_c1);
    cudaGetSymbolAddress((void**)&ph2, g_h2);
    cudaGetSymbolAddress((void**)&pc2, g_c2);

    float* h1buf[2] = { ph1, ph1 + (size_t)BB * HH };
    float* h2buf[2] = { ph2, ph2 + (size_t)BB * HH };

    dim3 grid(BB / BM, HH / 32);   // 16 x 16
    for (int t = 0; t < TT; t++) {
        int khT   = (t == 0) ? 0 : (HH / BK);
        int zeroc = (t == 0) ? 1 : 0;
        lstm_step_kernel<<<grid, NTHREADS>>>(
            x + (size_t)t * FF, TT * FF, FF / BK,
            h1buf[t & 1], khT,
            W1, U1, b1,
            pc1, zeroc,
            h1buf[(t + 1) & 1]);
        lstm_step_kernel<<<grid, NTHREADS>>>(
            h1buf[(t + 1) & 1], HH, HH / BK,
            h2buf[t & 1], khT,
            W2, U2, b2,
            pc2, zeroc,
            h2buf[(t + 1) & 1]);
    }
    dense_kernel<<<BB / 8, 256>>>(h2buf[0], Wd, bd, (float*)d_out);
}